// round 12
// baseline (speedup 1.0000x reference)
#include <cuda_runtime.h>
#include <cuda_bf16.h>
#include <math.h>
#include <stdint.h>

#define B_     1024
#define VOCAB  32000
#define D_     128
#define KNEG   5
#define ROWS_T 7168          // 1024 vi + 1024 vo + 5120 neg
#define RTILES 28            // 256-row tiles
#define SPLITS 5
#define CHUNK  6400          // VOCAB / SPLITS
#define ITERS  200           // CHUNK / 32

// smem:  A: [m=256][k=32] bf16, row pitch 80B.  B: [k=32][d=128] bf16,
// row 256B, 16B-chunk XOR-swizzled by (k&7).
// FOUR buffers each; __syncthreads only every 2 iterations.
#define A_ROWB  80
#define A_BUF   (256 * A_ROWB)    // 20480
#define B_BUF   (32 * 256)        // 8192
#define SMEM_DYN (4 * A_BUF + 4 * B_BUF)   // 114688 (dynamic)

// ---------------- device scratch ----------------
__device__ float g_part[SPLITS][ROWS_T][D_];   // split-K partials (18.3 MB)
__device__ float g_s[B_];
__device__ float g_bm[B_ * KNEG];

// ---------------- helpers ----------------
__device__ __forceinline__ uint32_t smem_u32(const void* p) {
    uint32_t a;
    asm("{ .reg .u64 t; cvta.to.shared.u64 t, %1; cvt.u32.u64 %0, t; }" : "=r"(a) : "l"(p));
    return a;
}
__device__ __forceinline__ uint32_t pack_bf16(float lo, float hi) {
    uint32_t u;
    asm("cvt.rn.bf16x2.f32 %0, %1, %2;" : "=r"(u) : "f"(hi), "f"(lo));
    return u;
}
__device__ __forceinline__ void ldsm4(uint32_t r[4], uint32_t addr) {
    asm volatile("ldmatrix.sync.aligned.m8n8.x4.shared.b16 {%0,%1,%2,%3}, [%4];"
                 : "=r"(r[0]), "=r"(r[1]), "=r"(r[2]), "=r"(r[3]) : "r"(addr));
}
__device__ __forceinline__ void ldsm4t(uint32_t r[4], uint32_t addr) {
    asm volatile("ldmatrix.sync.aligned.m8n8.x4.trans.shared.b16 {%0,%1,%2,%3}, [%4];"
                 : "=r"(r[0]), "=r"(r[1]), "=r"(r[2]), "=r"(r[3]) : "r"(addr));
}
__device__ __forceinline__ void mma16(float c[4], const uint32_t a[4], const uint32_t b[2]) {
    asm volatile(
        "mma.sync.aligned.m16n8k16.row.col.f32.bf16.bf16.f32 "
        "{%0,%1,%2,%3}, {%4,%5,%6,%7}, {%8,%9}, {%0,%1,%2,%3};"
        : "+f"(c[0]), "+f"(c[1]), "+f"(c[2]), "+f"(c[3])
        : "r"(a[0]), "r"(a[1]), "r"(a[2]), "r"(a[3]), "r"(b[0]), "r"(b[1]));
}

// ---------------- kernel 1: C_part[sp] = X_tile @ Y_chunk ----------------
// CTA tile 256m x 128n, BK=32.  8 warps as 4(m) x 2(n), warp tile 64x64.
// 4-stage smem ring; MMA(it) || STS(it+2) || LDG(it+3); barrier every 2 iters.
__global__ __launch_bounds__(256, 1) void gemm_all(const float* __restrict__ vi,
                                                   const float* __restrict__ vo,
                                                   const float* __restrict__ neg,
                                                   const float* __restrict__ V,
                                                   const float* __restrict__ U) {
    extern __shared__ __align__(16) char smem[];

    const int mt = blockIdx.x;                // row-tile 0..27
    const int sp = blockIdx.y;                // split   0..4
    const int row0 = mt * 256;
    const float* X = (mt < 4) ? vi  + (size_t)row0 * VOCAB
                   : (mt < 8) ? vo  + (size_t)(row0 - 1024) * VOCAB
                              : neg + (size_t)(row0 - 2048) * VOCAB;
    const float* Y = (mt < 4) ? V : U;
    const int kk0 = sp * CHUNK;

    const int tid = threadIdx.x, lane = tid & 31, wid = tid >> 5;
    const int wm = wid >> 1, wn = wid & 1;    // 4 x 2

    const uint32_t sb = smem_u32(smem);

    // ---- loader roles (coalesced; validated) ----
    const int ar = tid >> 3;                  // A: row within pass (s*32 + ar)
    const int ac = tid & 7;                   // A: float4 col
    const int br = tid >> 5;                  // B: row within pass (s*8 + br)
    const int bc = lane;                      // B: float4 col

    // ---- fragment addresses (validated maps; warp m-span 64) ----
    const uint32_t a_off = (uint32_t)(wm * 64 + (lane & 15)) * A_ROWB + ((lane >> 4) << 4);
    const int kl = (lane & 7) + ((lane >> 3) & 1) * 8;
    uint32_t b_swz[4];
    #pragma unroll
    for (int jj = 0; jj < 4; jj++)
        b_swz[jj] = (uint32_t)(((wn * 8 + jj * 2 + (lane >> 4)) ^ (lane & 7)) << 4);
    const uint32_t b_off = (uint32_t)kl * 256;

    float c[4][8][4] = {};
    float4 xa[8], yb[4];

    // ---- staging helpers ----
    auto do_ldg = [&](int it) {
        const int kk = kk0 + it * 32;
        #pragma unroll
        for (int s = 0; s < 8; s++)
            xa[s] = *(const float4*)(X + (size_t)(s * 32 + ar) * VOCAB + kk + ac * 4);
        #pragma unroll
        for (int s = 0; s < 4; s++)
            yb[s] = *(const float4*)(Y + (size_t)(kk + s * 8 + br) * D_ + bc * 4);
    };
    auto do_sts = [&](int buf) {
        char* abase = smem + (uint32_t)buf * A_BUF;
        #pragma unroll
        for (int s = 0; s < 8; s++) {
            uint2 v = make_uint2(pack_bf16(xa[s].x, xa[s].y),
                                 pack_bf16(xa[s].z, xa[s].w));
            *(uint2*)(abase + (s * 32 + ar) * A_ROWB + ac * 8) = v;
        }
        char* bbase = smem + 4 * A_BUF + (uint32_t)buf * B_BUF;
        #pragma unroll
        for (int s = 0; s < 4; s++) {
            int row = s * 8 + br;
            int chs = (bc >> 1) ^ (row & 7);
            uint2 v = make_uint2(pack_bf16(yb[s].x, yb[s].y),
                                 pack_bf16(yb[s].z, yb[s].w));
            *(uint2*)(bbase + row * 256 + chs * 16 + (bc & 1) * 8) = v;
        }
    };

    // ---- prologue: fill buf0/buf1, prefetch iter2 into regs ----
    do_ldg(0); do_sts(0);
    do_ldg(1); do_sts(1);
    do_ldg(2);
    __syncthreads();

    for (int it = 0; it < ITERS; it++) {
        const int buf = it & 3;
        const uint32_t abuf = sb + (uint32_t)buf * A_BUF;
        const uint32_t bbuf = sb + 4 * A_BUF + (uint32_t)buf * B_BUF;

        // ---- MMA on current buffer ----
        #pragma unroll
        for (int ks = 0; ks < 2; ks++) {
            uint32_t af[4][4];
            #pragma unroll
            for (int i = 0; i < 4; i++)
                ldsm4(af[i], abuf + a_off + i * (16 * A_ROWB) + ks * 32);
            const uint32_t brow_b = bbuf + b_off + ks * 16 * 256;
            #pragma unroll
            for (int jj = 0; jj < 4; jj++) {
                uint32_t bf[4];
                ldsm4t(bf, brow_b + b_swz[jj]);
                #pragma unroll
                for (int i = 0; i < 4; i++) {
                    mma16(c[i][jj * 2],     af[i], bf);
                    mma16(c[i][jj * 2 + 1], af[i], bf + 2);
                }
            }
        }

        // ---- stage it+2 (regs loaded two iters back), prefetch it+3 ----
        if (it + 2 < ITERS)
            do_sts((it + 2) & 3);
        if (it + 3 < ITERS)
            do_ldg(it + 3);

        // ---- barrier every SECOND iteration ----
        if ((it & 1) && (it + 1 < ITERS))
            __syncthreads();
    }

    // ---- epilogue: disjoint partial writes ----
    const int g = lane >> 2, t = lane & 3;
    float* P = &g_part[sp][row0][0];
    #pragma unroll
    for (int i = 0; i < 4; i++) {
        #pragma unroll
        for (int j = 0; j < 8; j++) {
            int m = wm * 64 + i * 16;
            int col = wn * 64 + j * 8 + 2 * t;
            *(float2*)&P[(size_t)(m + g) * D_ + col]     = make_float2(c[i][j][0], c[i][j][1]);
            *(float2*)&P[(size_t)(m + g + 8) * D_ + col] = make_float2(c[i][j][2], c[i][j][3]);
        }
    }
}

// ---------------- kernel 2: reduce partials + per-b dot products ----------------
__global__ __launch_bounds__(256) void finalize_a() {
    const int wid = threadIdx.x >> 5, lane = threadIdx.x & 31;
    const int b = blockIdx.x * 8 + wid;
    const int d = lane * 4;

    float4 e = make_float4(0.f, 0.f, 0.f, 0.f);
    float4 p = make_float4(0.f, 0.f, 0.f, 0.f);
    float4 nk[KNEG];
    #pragma unroll
    for (int k = 0; k < KNEG; k++) nk[k] = make_float4(0.f, 0.f, 0.f, 0.f);

    #pragma unroll
    for (int sp = 0; sp < SPLITS; sp++) {
        float4 v;
        v = *(const float4*)&g_part[sp][b][d];
        e.x += v.x; e.y += v.y; e.z += v.z; e.w += v.w;
        v = *(const float4*)&g_part[sp][1024 + b][d];
        p.x += v.x; p.y += v.y; p.z += v.z; p.w += v.w;
        #pragma unroll
        for (int k = 0; k < KNEG; k++) {
            v = *(const float4*)&g_part[sp][2048 + b * KNEG + k][d];
            nk[k].x += v.x; nk[k].y += v.y; nk[k].z += v.z; nk[k].w += v.w;
        }
    }

    float s = e.x * p.x + e.y * p.y + e.z * p.z + e.w * p.w;
    float bm[KNEG];
    #pragma unroll
    for (int k = 0; k < KNEG; k++)
        bm[k] = e.x * nk[k].x + e.y * nk[k].y + e.z * nk[k].z + e.w * nk[k].w;

    #pragma unroll
    for (int off = 16; off; off >>= 1) {
        s += __shfl_xor_sync(0xffffffffu, s, off);
        #pragma unroll
        for (int k = 0; k < KNEG; k++)
            bm[k] += __shfl_xor_sync(0xffffffffu, bm[k], off);
    }
    if (lane == 0) {
        g_s[b] = s;
        #pragma unroll
        for (int k = 0; k < KNEG; k++) g_bm[b * KNEG + k] = bm[k];
    }
}

// ---------------- kernel 3: loss ----------------
__device__ __forceinline__ float logsig(float x) {
    return fminf(x, 0.f) - log1pf(expf(-fabsf(x)));
}

__global__ void finalize_kernel(float* __restrict__ out) {
    __shared__ float red[B_];
    int b = threadIdx.x;
    float left  = logsig(g_s[b]);
    float right = 0.f;
    #pragma unroll
    for (int k = 0; k < KNEG; k++)
        right += logsig(-g_bm[b * KNEG + k]);
    red[b] = -(left + right);
    __syncthreads();
    for (int off = B_ / 2; off > 0; off >>= 1) {
        if (b < off) red[b] += red[b + off];
        __syncthreads();
    }
    if (b == 0) out[0] = red[0] / (float)B_;
}

// ---------------- launch ----------------
extern "C" void kernel_launch(void* const* d_in, const int* in_sizes, int n_in,
                              void* d_out, int out_size) {
    const float* vi  = (const float*)d_in[0];   // [B, VOC]
    const float* vo  = (const float*)d_in[1];   // [B, VOC]
    const float* neg = (const float*)d_in[2];   // [B, K, VOC]
    const float* V   = (const float*)d_in[3];   // [VOC, D]
    const float* U   = (const float*)d_in[4];   // [VOC, D]
    float* out = (float*)d_out;

    cudaFuncSetAttribute(gemm_all, cudaFuncAttributeMaxDynamicSharedMemorySize, SMEM_DYN);

    gemm_all<<<dim3(RTILES, SPLITS), 256, SMEM_DYN>>>(vi, vo, neg, V, U);
    finalize_a<<<B_ / 8, 256>>>();
    finalize_kernel<<<1, B_>>>(out);
}